// round 2
// baseline (speedup 1.0000x reference)
#include <cuda_runtime.h>
#include <cuda_fp16.h>
#include <cstdint>

// ---------------------------------------------------------------------------
// FlashMoERouter on GB300 (sm_103a, family-PTX-safe: mma.sync HMMA path)
//   [16384,4096] x [4096,128] fp32-accurate via fp16 2-way split:
//     scores = xh*wh + (xh*(2048*dw) + (2048*dx)*wh)/2048
//   capacity columns need only the hi pass (scale cancels in renorm).
//   Fused LN/GELU/sigmoid/top-2 epilogue.
// ---------------------------------------------------------------------------

#define SW128(o) ((o) ^ (((o) >> 3) & 0x70))

static constexpr int NTOK   = 16384;
static constexpr int DIM    = 4096;
static constexpr int NOUT   = 128;          // 64 gate + 64 cap hidden
static constexpr int NEXP   = 64;
static constexpr int MT     = 128;          // tokens per CTA
static constexpr int KC     = 64;           // K per chunk
static constexpr int NIT    = DIM / KC;     // 64 chunks
static constexpr int TILE_B = 128 * 128;    // fp16 [128 rows x 64 k] = 16KB

// smem layout
static constexpr int OFF_XH   = 0;
static constexpr int OFF_XL   = 16384;
static constexpr int OFF_WH   = 32768;
static constexpr int OFF_WL   = 49152;
static constexpr int BUF_B    = 65536;      // two buffers: 0, 65536
static constexpr int OFF_XRAW = 131072;     // two xraw buffers, 34816 each
static constexpr int XRAW_B   = 34816;      // 128 rows * 272B (68 floats, padded)
static constexpr int SMEM_SZ  = OFF_XRAW + 2 * XRAW_B;   // 200704

// Pre-split W scratch (swizzled, per-chunk tiles ready for linear cp.async)
__device__ __align__(16) unsigned char g_wh[NIT * TILE_B];
__device__ __align__(16) unsigned char g_wl[NIT * TILE_B];

// ---------------- helpers ----------------
__device__ __forceinline__ uint32_t smem_u32(const void* p) {
    uint32_t a;
    asm("{ .reg .u64 t; cvta.to.shared.u64 t, %1; cvt.u32.u64 %0, t; }"
        : "=r"(a) : "l"(p));
    return a;
}
__device__ __forceinline__ void cp_async16(uint32_t s, const void* g) {
    asm volatile("cp.async.cg.shared.global [%0], [%1], 16;" :: "r"(s), "l"(g) : "memory");
}
#define CP_COMMIT() asm volatile("cp.async.commit_group;" ::: "memory")
#define CP_WAIT0()  asm volatile("cp.async.wait_group 0;" ::: "memory")

__device__ __forceinline__ void ldsm4(uint32_t* r, uint32_t addr) {
    asm volatile("ldmatrix.sync.aligned.m8n8.x4.shared.b16 {%0,%1,%2,%3}, [%4];"
                 : "=r"(r[0]), "=r"(r[1]), "=r"(r[2]), "=r"(r[3]) : "r"(addr));
}
__device__ __forceinline__ void mma16816(float* d, const uint32_t* a,
                                         uint32_t b0, uint32_t b1) {
    asm volatile(
        "mma.sync.aligned.m16n8k16.row.col.f32.f16.f16.f32 "
        "{%0,%1,%2,%3}, {%4,%5,%6,%7}, {%8,%9}, {%0,%1,%2,%3};"
        : "+f"(d[0]), "+f"(d[1]), "+f"(d[2]), "+f"(d[3])
        : "r"(a[0]), "r"(a[1]), "r"(a[2]), "r"(a[3]), "r"(b0), "r"(b1));
}
__device__ __forceinline__ float wsum(float v) {
#pragma unroll
    for (int o = 16; o; o >>= 1) v += __shfl_xor_sync(0xffffffffu, v, o);
    return v;
}
__device__ __forceinline__ bool better(float v, int i, float w, int j) {
    return (v > w) || (v == w && i < j);
}

// ---------------- prep: split W=[gate_w;cap_w1] into swizzled fp16 tiles ----
__global__ void prep_kernel(const float* __restrict__ gate_w,
                            const float* __restrict__ cap_w1) {
    int idx = blockIdx.x * blockDim.x + threadIdx.x;
    if (idx >= NOUT * DIM) return;
    int n = idx >> 12;
    int k = idx & (DIM - 1);
    float w = (n < NEXP) ? gate_w[n * DIM + k] : cap_w1[(n - NEXP) * DIM + k];
    __half wh = __float2half_rn(w);
    float res = (w - __half2float(wh)) * 2048.0f;
    __half wl = __float2half_rn(res);
    int t = k >> 6, kk = k & 63;
    int off = SW128(n * 128 + kk * 2);
    *(__half*)(g_wh + t * TILE_B + off) = wh;
    *(__half*)(g_wl + t * TILE_B + off) = wl;
}

// ---------------- main kernel (256 threads, 8 warps) ----------------
__global__ void __launch_bounds__(256, 1)
router_kernel(const float* __restrict__ x,
              const float* __restrict__ cap_b1, const float* __restrict__ ln_g,
              const float* __restrict__ ln_b,   const float* __restrict__ cap_w2,
              const float* __restrict__ cap_b2, const float* __restrict__ temp,
              const float* __restrict__ usage,  float* __restrict__ out) {
    extern __shared__ char smem[];
    const uint32_t sb = smem_u32(smem);
    const int tid  = threadIdx.x;
    const int wid  = tid >> 5;
    const int lane = tid & 31;
    const int tok0 = blockIdx.x * MT;

    // warp roles: mt in {0,1} (rows mt*64), role in {0:gate-hi, 1/2:gate-lo, 3:cap-hi}
    const int mt      = wid >> 2;
    const int role    = wid & 3;
    const int rowbase = mt * 64;
    const bool isLo   = (role == 1 || role == 2);
    const int nbase   = (role == 0) ? 0 : (role == 3 ? 64 : (role - 1) * 32);

    // ldmatrix lane addressing
    const int g  = lane >> 3;
    const int lr = lane & 7;
    const uint32_t rowOffA = (uint32_t)(rowbase + (g & 1) * 8 + lr) * 128;
    const uint32_t rowOffB = (uint32_t)(nbase   + (g & 1) * 8 + lr) * 128;
    const uint32_t kxbase  = (uint32_t)(((g >> 1) ^ lr) << 4);

    float acc[4][8][4];
#pragma unroll
    for (int i = 0; i < 4; i++)
#pragma unroll
        for (int j = 0; j < 8; j++)
#pragma unroll
            for (int c = 0; c < 4; c++) acc[i][j][c] = 0.0f;

    // cp.async issue lambda-ish: W tiles + raw x chunk
    auto issue_loads = [&](int chunk, int buf) {
        const uint32_t wdst = sb + buf * BUF_B;
        const unsigned char* whsrc = g_wh + chunk * TILE_B;
        const unsigned char* wlsrc = g_wl + chunk * TILE_B;
#pragma unroll
        for (int t = 0; t < 4; t++) {
            int j = tid + t * 256;                 // 1024 x 16B
            cp_async16(wdst + OFF_WH + j * 16, whsrc + j * 16);
            cp_async16(wdst + OFF_WL + j * 16, wlsrc + j * 16);
        }
        const uint32_t xdst = sb + OFF_XRAW + buf * XRAW_B;
#pragma unroll
        for (int t = 0; t < 8; t++) {
            int c = tid + t * 256;                 // 2048 x 16B
            int row = c >> 4, kc = c & 15;
            cp_async16(xdst + row * 272 + kc * 16,
                       x + (size_t)(tok0 + row) * DIM + chunk * KC + kc * 4);
        }
        CP_COMMIT();
    };

    // convert raw fp32 chunk -> swizzled (xh, xl) fp16 tiles
    auto convert = [&](int buf) {
        const float* xr = (const float*)(smem + OFF_XRAW + buf * XRAW_B);
        char* dsth = smem + buf * BUF_B + OFF_XH;
        char* dstl = smem + buf * BUF_B + OFF_XL;
        const int r = tid & 127, h2 = tid >> 7;
        const uint32_t xr0 = (uint32_t)r * 68 + h2 * 32;
        const uint32_t so0 = ((uint32_t)r * 128 + h2 * 64) ^ ((r & 7) << 4);
#pragma unroll
        for (int j = 0; j < 8; j++) {
            float4 f = *(const float4*)(xr + xr0 + j * 4);
            __half h0 = __float2half_rn(f.x), h1 = __float2half_rn(f.y);
            __half h2a = __float2half_rn(f.z), h3 = __float2half_rn(f.w);
            float l0 = (f.x - __half2float(h0)) * 2048.0f;
            float l1 = (f.y - __half2float(h1)) * 2048.0f;
            float l2 = (f.z - __half2float(h2a)) * 2048.0f;
            float l3 = (f.w - __half2float(h3)) * 2048.0f;
            __half2 hh01 = __halves2half2(h0, h1), hh23 = __halves2half2(h2a, h3);
            __half2 ll01 = __halves2half2(__float2half_rn(l0), __float2half_rn(l1));
            __half2 ll23 = __halves2half2(__float2half_rn(l2), __float2half_rn(l3));
            uint32_t o = so0 ^ (uint32_t)(j * 8);   // j*8 within bits 3-6, xor-safe
            *(uint2*)(dsth + o) = make_uint2(*(uint32_t*)&hh01, *(uint32_t*)&hh23);
            *(uint2*)(dstl + o) = make_uint2(*(uint32_t*)&ll01, *(uint32_t*)&ll23);
        }
    };

    // prologue: chunk 0
    issue_loads(0, 0);
    CP_WAIT0();
    __syncthreads();
    convert(0);
    __syncthreads();

#pragma unroll 1
    for (int i = 0; i < NIT; i++) {
        const int c = i & 1, n = c ^ 1;
        if (i + 1 < NIT) issue_loads(i + 1, n);

        const uint32_t bufc = sb + c * BUF_B;
        const uint32_t aXH = bufc + OFF_XH + rowOffA;
        const uint32_t aXL = bufc + OFF_XL + rowOffA;
        const uint32_t bWH = bufc + OFF_WH + rowOffB;
        const uint32_t bWL = bufc + OFF_WL + rowOffB;

#pragma unroll
        for (int ks = 0; ks < 4; ks++) {
            const uint32_t koff = ((uint32_t)ks * 32) ^ kxbase;
            if (!isLo) {
                uint32_t a[4][4], b[4][4];
#pragma unroll
                for (int mi = 0; mi < 4; mi++) ldsm4(a[mi], aXH + mi * 2048 + koff);
#pragma unroll
                for (int nj = 0; nj < 4; nj++) ldsm4(b[nj], bWH + nj * 2048 + koff);
#pragma unroll
                for (int mi = 0; mi < 4; mi++)
#pragma unroll
                    for (int nj = 0; nj < 4; nj++) {
                        mma16816(acc[mi][2 * nj],     a[mi], b[nj][0], b[nj][2]);
                        mma16816(acc[mi][2 * nj + 1], a[mi], b[nj][1], b[nj][3]);
                    }
            } else {
                uint32_t ah[4][4], al[4][4], bh[2][4], bl[2][4];
#pragma unroll
                for (int mi = 0; mi < 4; mi++) {
                    ldsm4(ah[mi], aXH + mi * 2048 + koff);
                    ldsm4(al[mi], aXL + mi * 2048 + koff);
                }
#pragma unroll
                for (int nj = 0; nj < 2; nj++) {
                    ldsm4(bl[nj], bWL + nj * 2048 + koff);
                    ldsm4(bh[nj], bWH + nj * 2048 + koff);
                }
#pragma unroll
                for (int mi = 0; mi < 4; mi++)
#pragma unroll
                    for (int nj = 0; nj < 2; nj++) {
                        mma16816(acc[mi][2 * nj],     ah[mi], bl[nj][0], bl[nj][2]);
                        mma16816(acc[mi][2 * nj + 1], ah[mi], bl[nj][1], bl[nj][3]);
                        mma16816(acc[mi][2 * nj],     al[mi], bh[nj][0], bh[nj][2]);
                        mma16816(acc[mi][2 * nj + 1], al[mi], bh[nj][1], bh[nj][3]);
                    }
            }
        }

        if (i + 1 < NIT) {
            CP_WAIT0();
            __syncthreads();
            convert(n);
            __syncthreads();
        }
    }
    __syncthreads();   // all ldmatrix done; smem free for epilogue

    // ---- epilogue A: accumulators -> smem ----
    float* sc = (float*)smem;                 // [128][129] hi scores (gate+cap)
    float* lo = (float*)(smem + 66048);       // [128][65]  gate correction
    {
        const int r4 = lane >> 2, c2 = (lane & 3) * 2;
        if (!isLo) {
            const int cb = (role == 3) ? 64 : 0;
#pragma unroll
            for (int mi = 0; mi < 4; mi++)
#pragma unroll
                for (int nj = 0; nj < 8; nj++) {
                    int row = rowbase + mi * 16 + r4;
                    int col = cb + nj * 8 + c2;
                    sc[row * 129 + col]       = acc[mi][nj][0];
                    sc[row * 129 + col + 1]   = acc[mi][nj][1];
                    sc[(row + 8) * 129 + col]     = acc[mi][nj][2];
                    sc[(row + 8) * 129 + col + 1] = acc[mi][nj][3];
                }
        } else {
            const int cb = (role - 1) * 32;
#pragma unroll
            for (int mi = 0; mi < 4; mi++)
#pragma unroll
                for (int nj = 0; nj < 4; nj++) {
                    int row = rowbase + mi * 16 + r4;
                    int col = cb + nj * 8 + c2;
                    lo[row * 65 + col]       = acc[mi][nj][0];
                    lo[row * 65 + col + 1]   = acc[mi][nj][1];
                    lo[(row + 8) * 65 + col]     = acc[mi][nj][2];
                    lo[(row + 8) * 65 + col + 1] = acc[mi][nj][3];
                }
        }
    }
    __syncthreads();

    // ---- epilogue B: per-token routing (8 warps x 16 tokens) ----
    const float u_a = usage[lane], u_b = usage[lane + 32];
    const float utot = wsum(u_a + u_b);
    const float lbs  = 0.1f / (utot + 1e-6f);
    const float lbp_a = u_a * lbs, lbp_b = u_b * lbs;
    const float tclip = fmaxf(temp[0], 0.1f);
    const float cb1a = cap_b1[lane],  cb1b = cap_b1[lane + 32];
    const float ga   = ln_g[lane],    gb   = ln_g[lane + 32];
    const float ba   = ln_b[lane],    bb   = ln_b[lane + 32];
    const float w2a  = cap_w2[lane],  w2b  = cap_w2[lane + 32];
    const float b2   = cap_b2[0];
    const float INV2048 = 4.8828125e-4f;

#pragma unroll 1
    for (int j = 0; j < 16; j++) {
        const int tl = wid * 16 + j;
        const float* srow = sc + tl * 129;
        const float* lrow = lo + tl * 65;
        const float s_a = srow[lane]      + lrow[lane]      * INV2048;
        const float s_b = srow[lane + 32] + lrow[lane + 32] * INV2048;
        const float h_a = srow[64 + lane] + cb1a;
        const float h_b = srow[96 + lane] + cb1b;

        const float mu  = wsum(h_a + h_b) * (1.0f / 64.0f);
        const float msq = wsum(h_a * h_a + h_b * h_b) * (1.0f / 64.0f);
        const float rstd = rsqrtf(msq - mu * mu + 1e-5f);
        const float na = (h_a - mu) * rstd * ga + ba;
        const float nb = (h_b - mu) * rstd * gb + bb;
        const float ge_a = 0.5f * na * (1.0f + erff(na * 0.70710678118654752f));
        const float ge_b = 0.5f * nb * (1.0f + erff(nb * 0.70710678118654752f));
        const float z = wsum(ge_a * w2a + ge_b * w2b) + b2;
        const float cap = 1.0f / (1.0f + expf(-z));
        const float scale = cap * tclip;

        const float gta = (s_a - lbp_a) * scale;
        const float gtb = (s_b - lbp_b) * scale;

        float v1, v2; int i1, i2;
        if (better(gta, lane, gtb, lane + 32)) { v1 = gta; i1 = lane;      v2 = gtb; i2 = lane + 32; }
        else                                   { v1 = gtb; i1 = lane + 32; v2 = gta; i2 = lane; }
#pragma unroll
        for (int o = 16; o; o >>= 1) {
            float ov1 = __shfl_xor_sync(0xffffffffu, v1, o);
            int   oi1 = __shfl_xor_sync(0xffffffffu, i1, o);
            float ov2 = __shfl_xor_sync(0xffffffffu, v2, o);
            int   oi2 = __shfl_xor_sync(0xffffffffu, i2, o);
            if (better(ov1, oi1, v1, i1)) {
                float c2v; int c2i;
                if (better(v1, i1, ov2, oi2)) { c2v = v1; c2i = i1; }
                else                          { c2v = ov2; c2i = oi2; }
                v1 = ov1; i1 = oi1; v2 = c2v; i2 = c2i;
            } else if (better(ov1, oi1, v2, i2)) {
                v2 = ov1; i2 = oi1;
            }
        }
        const float inv = 1.0f / (v1 + v2 + 1e-6f);
        const size_t ob = (size_t)(tok0 + tl) * 64;
        out[ob + lane]      = (lane == i1)      ? v1 * inv : ((lane == i2)      ? v2 * inv : 0.0f);
        out[ob + lane + 32] = (lane + 32 == i1) ? v1 * inv : ((lane + 32 == i2) ? v2 * inv : 0.0f);
    }
}

// ---------------- launch ----------------
extern "C" void kernel_launch(void* const* d_in, const int* in_sizes, int n_in,
                              void* d_out, int out_size) {
    const float* x      = (const float*)d_in[0];
    const float* gate_w = (const float*)d_in[1];
    const float* cap_w1 = (const float*)d_in[2];
    const float* cap_b1 = (const float*)d_in[3];
    const float* ln_g   = (const float*)d_in[4];
    const float* ln_b   = (const float*)d_in[5];
    const float* cap_w2 = (const float*)d_in[6];
    const float* cap_b2 = (const float*)d_in[7];
    const float* temp   = (const float*)d_in[8];
    const float* usage  = (const float*)d_in[9];
    float* out = (float*)d_out;

    cudaFuncSetAttribute(router_kernel,
                         cudaFuncAttributeMaxDynamicSharedMemorySize, SMEM_SZ);

    prep_kernel<<<(NOUT * DIM) / 256, 256>>>(gate_w, cap_w1);
    router_kernel<<<NTOK / MT, 256, SMEM_SZ>>>(x, cap_b1, ln_g, ln_b, cap_w2,
                                               cap_b2, temp, usage, out);
}

// round 3
// speedup vs baseline: 1.1832x; 1.1832x over previous
#include <cuda_runtime.h>
#include <cuda_fp16.h>
#include <cstdint>

// ---------------------------------------------------------------------------
// FlashMoERouter on GB300 (sm_103a) — HMMA mma.sync path, fp16 2-way split.
// R3: 512 threads (16 warps), reg-staged x convert, 1 sync/iter.
// ---------------------------------------------------------------------------

#define SW128(o) ((o) ^ (((o) >> 3) & 0x70))

static constexpr int NTOK   = 16384;
static constexpr int DIM    = 4096;
static constexpr int NOUT   = 128;
static constexpr int NEXP   = 64;
static constexpr int MT     = 128;          // tokens per CTA
static constexpr int KC     = 64;           // K per chunk
static constexpr int NIT    = DIM / KC;     // 64
static constexpr int TILE_B = 128 * 128;    // 16KB fp16 [128 x 64]

static constexpr int OFF_XH = 0;
static constexpr int OFF_XL = 16384;
static constexpr int OFF_WH = 32768;
static constexpr int OFF_WL = 49152;
static constexpr int BUF_B  = 65536;
// epilogue: sc[128][129] f32 (66048B), lo1[128][65] (33280B), lo2[128][65]
static constexpr int EPI_LO1 = 66048;
static constexpr int EPI_LO2 = 99328;
static constexpr int SMEM_SZ = 132608;      // max(2*BUF_B, epilogue)

__device__ __align__(16) unsigned char g_wh[NIT * TILE_B];
__device__ __align__(16) unsigned char g_wl[NIT * TILE_B];

// ---------------- helpers ----------------
__device__ __forceinline__ uint32_t smem_u32(const void* p) {
    uint32_t a;
    asm("{ .reg .u64 t; cvta.to.shared.u64 t, %1; cvt.u32.u64 %0, t; }"
        : "=r"(a) : "l"(p));
    return a;
}
__device__ __forceinline__ void cp_async16(uint32_t s, const void* g) {
    asm volatile("cp.async.cg.shared.global [%0], [%1], 16;" :: "r"(s), "l"(g) : "memory");
}
#define CP_COMMIT() asm volatile("cp.async.commit_group;" ::: "memory")
#define CP_WAIT0()  asm volatile("cp.async.wait_group 0;" ::: "memory")

__device__ __forceinline__ void ldsm4(uint32_t* r, uint32_t addr) {
    asm volatile("ldmatrix.sync.aligned.m8n8.x4.shared.b16 {%0,%1,%2,%3}, [%4];"
                 : "=r"(r[0]), "=r"(r[1]), "=r"(r[2]), "=r"(r[3]) : "r"(addr));
}
__device__ __forceinline__ void mma16816(float* d, const uint32_t* a,
                                         uint32_t b0, uint32_t b1) {
    asm volatile(
        "mma.sync.aligned.m16n8k16.row.col.f32.f16.f16.f32 "
        "{%0,%1,%2,%3}, {%4,%5,%6,%7}, {%8,%9}, {%0,%1,%2,%3};"
        : "+f"(d[0]), "+f"(d[1]), "+f"(d[2]), "+f"(d[3])
        : "r"(a[0]), "r"(a[1]), "r"(a[2]), "r"(a[3]), "r"(b0), "r"(b1));
}
__device__ __forceinline__ float wsum(float v) {
#pragma unroll
    for (int o = 16; o; o >>= 1) v += __shfl_xor_sync(0xffffffffu, v, o);
    return v;
}
__device__ __forceinline__ bool better(float v, int i, float w, int j) {
    return (v > w) || (v == w && i < j);
}

// ---------------- prep: split W into swizzled fp16 tiles ----------------
__global__ void prep_kernel(const float* __restrict__ gate_w,
                            const float* __restrict__ cap_w1) {
    int idx = blockIdx.x * blockDim.x + threadIdx.x;
    if (idx >= NOUT * DIM) return;
    int n = idx >> 12;
    int k = idx & (DIM - 1);
    float w = (n < NEXP) ? gate_w[n * DIM + k] : cap_w1[(n - NEXP) * DIM + k];
    __half wh = __float2half_rn(w);
    float res = (w - __half2float(wh)) * 2048.0f;
    __half wl = __float2half_rn(res);
    int t = k >> 6, kk = k & 63;
    int off = SW128(n * 128 + kk * 2);
    *(__half*)(g_wh + t * TILE_B + off) = wh;
    *(__half*)(g_wl + t * TILE_B + off) = wl;
}

// ---------------- main kernel: 512 threads, 16 warps ----------------
__global__ void __launch_bounds__(512, 1)
router_kernel(const float* __restrict__ x,
              const float* __restrict__ cap_b1, const float* __restrict__ ln_g,
              const float* __restrict__ ln_b,   const float* __restrict__ cap_w2,
              const float* __restrict__ cap_b2, const float* __restrict__ temp,
              const float* __restrict__ usage,  float* __restrict__ out) {
    extern __shared__ char smem[];
    const uint32_t sb = smem_u32(smem);
    const int tid  = threadIdx.x;
    const int wid  = tid >> 5;
    const int lane = tid & 31;
    const int tok0 = blockIdx.x * MT;

    // 16 warp tiles, each M64 x N32:
    //   p = wid>>1: 0-3 hi pass (N = p*32 over 128 cols: gate 0-63 | cap 64-127)
    //               4-5 lo1 = xh*wl (gate cols 0-63), 6-7 lo2 = xl*wh
    const int mt      = wid & 1;
    const int p       = wid >> 1;
    const int rowbase = mt * 64;
    const int nbase   = (p < 4) ? p * 32 : (p & 1) * 32;
    const int aOff    = (p >= 6) ? OFF_XL : OFF_XH;
    const int bOff    = (p == 4 || p == 5) ? OFF_WL : OFF_WH;

    const int g  = lane >> 3;
    const int lr = lane & 7;
    const uint32_t rowA0 = (uint32_t)(rowbase + (g & 1) * 8 + lr) * 128;
    const uint32_t rowB0 = (uint32_t)(nbase   + (g & 1) * 8 + lr) * 128;
    const uint32_t kx    = (uint32_t)(((g >> 1) ^ lr) << 4);

    float acc[4][4][4];
#pragma unroll
    for (int a = 0; a < 4; a++)
#pragma unroll
        for (int b = 0; b < 4; b++)
#pragma unroll
            for (int c = 0; c < 4; c++) acc[a][b][c] = 0.0f;

    // x producer addressing: thread -> (row = tid>>2, 16 k at q*16)
    const int xr = tid >> 2, xq = tid & 3;
    const float* xptr = x + (size_t)(tok0 + xr) * DIM + xq * 16;
    const uint32_t s0 = SW128((uint32_t)(xr * 128 + xq * 32));
    const uint32_t s1 = SW128((uint32_t)(xr * 128 + xq * 32 + 16));

    auto issueW = [&](int chunk, int buf) {
        const uint32_t wdst = sb + buf * BUF_B;
        const unsigned char* whs = g_wh + chunk * TILE_B;
        const unsigned char* wls = g_wl + chunk * TILE_B;
        cp_async16(wdst + OFF_WH + tid * 16,          whs + tid * 16);
        cp_async16(wdst + OFF_WH + (tid + 512) * 16,  whs + (tid + 512) * 16);
        cp_async16(wdst + OFF_WL + tid * 16,          wls + tid * 16);
        cp_async16(wdst + OFF_WL + (tid + 512) * 16,  wls + (tid + 512) * 16);
        CP_COMMIT();
    };

    auto convert = [&](const float4* xf, int buf) {
        char* dh = smem + buf * BUF_B + OFF_XH;
        char* dl = smem + buf * BUF_B + OFF_XL;
        uint32_t hp[8], lp[8];
#pragma unroll
        for (int m = 0; m < 4; m++) {
            float4 f = xf[m];
            __half2 hA = __float22half2_rn(make_float2(f.x, f.y));
            __half2 hB = __float22half2_rn(make_float2(f.z, f.w));
            float2 gA = __half22float2(hA);
            float2 gB = __half22float2(hB);
            __half2 lA = __float22half2_rn(
                make_float2((f.x - gA.x) * 2048.0f, (f.y - gA.y) * 2048.0f));
            __half2 lB = __float22half2_rn(
                make_float2((f.z - gB.x) * 2048.0f, (f.w - gB.y) * 2048.0f));
            hp[2 * m]     = *(uint32_t*)&hA;
            hp[2 * m + 1] = *(uint32_t*)&hB;
            lp[2 * m]     = *(uint32_t*)&lA;
            lp[2 * m + 1] = *(uint32_t*)&lB;
        }
        *(uint4*)(dh + s0) = make_uint4(hp[0], hp[1], hp[2], hp[3]);
        *(uint4*)(dh + s1) = make_uint4(hp[4], hp[5], hp[6], hp[7]);
        *(uint4*)(dl + s0) = make_uint4(lp[0], lp[1], lp[2], lp[3]);
        *(uint4*)(dl + s1) = make_uint4(lp[4], lp[5], lp[6], lp[7]);
    };

    auto mmaPhase = [&](int buf) {
        const uint32_t aB = sb + buf * BUF_B + aOff + rowA0;
        const uint32_t bB = sb + buf * BUF_B + bOff + rowB0;
#pragma unroll
        for (int ks = 0; ks < 4; ks++) {
            const uint32_t ko = ((uint32_t)ks * 32) ^ kx;
            uint32_t a[4][4], b[2][4];
#pragma unroll
            for (int mi = 0; mi < 4; mi++) ldsm4(a[mi], aB + mi * 2048 + ko);
#pragma unroll
            for (int nj = 0; nj < 2; nj++) ldsm4(b[nj], bB + nj * 2048 + ko);
#pragma unroll
            for (int mi = 0; mi < 4; mi++)
#pragma unroll
                for (int nj = 0; nj < 2; nj++) {
                    mma16816(acc[mi][2 * nj],     a[mi], b[nj][0], b[nj][2]);
                    mma16816(acc[mi][2 * nj + 1], a[mi], b[nj][1], b[nj][3]);
                }
        }
    };

    // prologue: fill buffer 0
    float4 xf[4];
    issueW(0, 0);
    {
        const float4* px = (const float4*)xptr;
#pragma unroll
        for (int m = 0; m < 4; m++) xf[m] = px[m];
    }
    convert(xf, 0);
    CP_WAIT0();
    __syncthreads();

#pragma unroll 1
    for (int i = 0; i < NIT; i++) {
        const int c = i & 1, n = c ^ 1;
        if (i + 1 < NIT) {
            issueW(i + 1, n);
            const float4* px = (const float4*)(xptr + (i + 1) * KC);
#pragma unroll
            for (int m = 0; m < 4; m++) xf[m] = px[m];
        }
        mmaPhase(c);
        if (i + 1 < NIT) {
            convert(xf, n);
            CP_WAIT0();
        }
        __syncthreads();
    }

    // ---- epilogue A: accumulators -> smem ----
    float* sc  = (float*)smem;                   // [128][129]
    float* lo1 = (float*)(smem + EPI_LO1);       // [128][65]
    float* lo2 = (float*)(smem + EPI_LO2);       // [128][65]
    {
        float* dst; int stride;
        if (p < 4)      { dst = sc;  stride = 129; }
        else if (p < 6) { dst = lo1; stride = 65;  }
        else            { dst = lo2; stride = 65;  }
        const int r4 = lane >> 2, c2 = (lane & 3) * 2;
#pragma unroll
        for (int mi = 0; mi < 4; mi++)
#pragma unroll
            for (int n8 = 0; n8 < 4; n8++) {
                int row = rowbase + mi * 16 + r4;
                int col = nbase + n8 * 8 + c2;
                dst[row * stride + col]           = acc[mi][n8][0];
                dst[row * stride + col + 1]       = acc[mi][n8][1];
                dst[(row + 8) * stride + col]     = acc[mi][n8][2];
                dst[(row + 8) * stride + col + 1] = acc[mi][n8][3];
            }
    }
    __syncthreads();

    // ---- epilogue B: per-token routing (16 warps x 8 tokens) ----
    const float u_a = usage[lane], u_b = usage[lane + 32];
    const float utot = wsum(u_a + u_b);
    const float lbs  = 0.1f / (utot + 1e-6f);
    const float lbp_a = u_a * lbs, lbp_b = u_b * lbs;
    const float tclip = fmaxf(temp[0], 0.1f);
    const float cb1a = cap_b1[lane],  cb1b = cap_b1[lane + 32];
    const float ga   = ln_g[lane],    gb   = ln_g[lane + 32];
    const float ba   = ln_b[lane],    bb   = ln_b[lane + 32];
    const float w2a  = cap_w2[lane],  w2b  = cap_w2[lane + 32];
    const float b2   = cap_b2[0];
    const float INV2048 = 4.8828125e-4f;

#pragma unroll 1
    for (int j = 0; j < 8; j++) {
        const int tl = wid * 8 + j;
        const float* srow  = sc  + tl * 129;
        const float* l1row = lo1 + tl * 65;
        const float* l2row = lo2 + tl * 65;
        const float s_a = srow[lane]      + (l1row[lane]      + l2row[lane])      * INV2048;
        const float s_b = srow[lane + 32] + (l1row[lane + 32] + l2row[lane + 32]) * INV2048;
        const float h_a = srow[64 + lane] + cb1a;
        const float h_b = srow[96 + lane] + cb1b;

        const float mu  = wsum(h_a + h_b) * (1.0f / 64.0f);
        const float msq = wsum(h_a * h_a + h_b * h_b) * (1.0f / 64.0f);
        const float rstd = rsqrtf(msq - mu * mu + 1e-5f);
        const float na = (h_a - mu) * rstd * ga + ba;
        const float nb = (h_b - mu) * rstd * gb + bb;
        const float ge_a = 0.5f * na * (1.0f + erff(na * 0.70710678118654752f));
        const float ge_b = 0.5f * nb * (1.0f + erff(nb * 0.70710678118654752f));
        const float z = wsum(ge_a * w2a + ge_b * w2b) + b2;
        const float cap = 1.0f / (1.0f + expf(-z));
        const float scale = cap * tclip;

        const float gta = (s_a - lbp_a) * scale;
        const float gtb = (s_b - lbp_b) * scale;

        float v1, v2; int i1, i2;
        if (better(gta, lane, gtb, lane + 32)) { v1 = gta; i1 = lane;      v2 = gtb; i2 = lane + 32; }
        else                                   { v1 = gtb; i1 = lane + 32; v2 = gta; i2 = lane; }
#pragma unroll
        for (int o = 16; o; o >>= 1) {
            float ov1 = __shfl_xor_sync(0xffffffffu, v1, o);
            int   oi1 = __shfl_xor_sync(0xffffffffu, i1, o);
            float ov2 = __shfl_xor_sync(0xffffffffu, v2, o);
            int   oi2 = __shfl_xor_sync(0xffffffffu, i2, o);
            if (better(ov1, oi1, v1, i1)) {
                float c2v; int c2i;
                if (better(v1, i1, ov2, oi2)) { c2v = v1; c2i = i1; }
                else                          { c2v = ov2; c2i = oi2; }
                v1 = ov1; i1 = oi1; v2 = c2v; i2 = c2i;
            } else if (better(ov1, oi1, v2, i2)) {
                v2 = ov1; i2 = oi1;
            }
        }
        const float inv = 1.0f / (v1 + v2 + 1e-6f);
        const size_t ob = (size_t)(tok0 + tl) * 64;
        out[ob + lane]      = (lane == i1)      ? v1 * inv : ((lane == i2)      ? v2 * inv : 0.0f);
        out[ob + lane + 32] = (lane + 32 == i1) ? v1 * inv : ((lane + 32 == i2) ? v2 * inv : 0.0f);
    }
}

// ---------------- launch ----------------
extern "C" void kernel_launch(void* const* d_in, const int* in_sizes, int n_in,
                              void* d_out, int out_size) {
    const float* x      = (const float*)d_in[0];
    const float* gate_w = (const float*)d_in[1];
    const float* cap_w1 = (const float*)d_in[2];
    const float* cap_b1 = (const float*)d_in[3];
    const float* ln_g   = (const float*)d_in[4];
    const float* ln_b   = (const float*)d_in[5];
    const float* cap_w2 = (const float*)d_in[6];
    const float* cap_b2 = (const float*)d_in[7];
    const float* temp   = (const float*)d_in[8];
    const float* usage  = (const float*)d_in[9];
    float* out = (float*)d_out;

    cudaFuncSetAttribute(router_kernel,
                         cudaFuncAttributeMaxDynamicSharedMemorySize, SMEM_SZ);

    prep_kernel<<<(NOUT * DIM) / 256, 256>>>(gate_w, cap_w1);
    router_kernel<<<NTOK / MT, 512, SMEM_SZ>>>(x, cap_b1, ln_g, ln_b, cap_w2,
                                               cap_b2, temp, usage, out);
}

// round 4
// speedup vs baseline: 1.1958x; 1.0106x over previous
#include <cuda_runtime.h>
#include <cuda_fp16.h>
#include <cstdint>

// ---------------------------------------------------------------------------
// FlashMoERouter on GB300 (sm_103a) — HMMA mma.sync, fp16 2-way split.
// R4: 3-stage cp.async pipeline (wait_group 1), 512 threads, 1 sync/iter.
// ---------------------------------------------------------------------------

#define SW128(o) ((o) ^ (((o) >> 3) & 0x70))

static constexpr int NTOK   = 16384;
static constexpr int DIM    = 4096;
static constexpr int NOUT   = 128;
static constexpr int NEXP   = 64;
static constexpr int MT     = 128;
static constexpr int KC     = 64;
static constexpr int NIT    = DIM / KC;     // 64
static constexpr int TILE_B = 128 * 128;    // 16KB

static constexpr int OFF_XH = 0;
static constexpr int OFF_XL = 16384;
static constexpr int OFF_WH = 32768;
static constexpr int OFF_WL = 49152;
static constexpr int BUF_B  = 65536;
static constexpr int NSTAGE = 3;
static constexpr int EPI_LO1 = 66048;
static constexpr int EPI_LO2 = 99328;
static constexpr int SMEM_SZ = NSTAGE * BUF_B;   // 196608

__device__ __align__(16) unsigned char g_wh[NIT * TILE_B];
__device__ __align__(16) unsigned char g_wl[NIT * TILE_B];

// ---------------- helpers ----------------
__device__ __forceinline__ uint32_t smem_u32(const void* p) {
    uint32_t a;
    asm("{ .reg .u64 t; cvta.to.shared.u64 t, %1; cvt.u32.u64 %0, t; }"
        : "=r"(a) : "l"(p));
    return a;
}
__device__ __forceinline__ void cp_async16(uint32_t s, const void* g) {
    asm volatile("cp.async.cg.shared.global [%0], [%1], 16;" :: "r"(s), "l"(g) : "memory");
}
#define CP_COMMIT() asm volatile("cp.async.commit_group;" ::: "memory")
#define CP_WAIT0()  asm volatile("cp.async.wait_group 0;" ::: "memory")
#define CP_WAIT1()  asm volatile("cp.async.wait_group 1;" ::: "memory")

__device__ __forceinline__ void ldsm4(uint32_t* r, uint32_t addr) {
    asm volatile("ldmatrix.sync.aligned.m8n8.x4.shared.b16 {%0,%1,%2,%3}, [%4];"
                 : "=r"(r[0]), "=r"(r[1]), "=r"(r[2]), "=r"(r[3]) : "r"(addr));
}
__device__ __forceinline__ void mma16816(float* d, const uint32_t* a,
                                         uint32_t b0, uint32_t b1) {
    asm volatile(
        "mma.sync.aligned.m16n8k16.row.col.f32.f16.f16.f32 "
        "{%0,%1,%2,%3}, {%4,%5,%6,%7}, {%8,%9}, {%0,%1,%2,%3};"
        : "+f"(d[0]), "+f"(d[1]), "+f"(d[2]), "+f"(d[3])
        : "r"(a[0]), "r"(a[1]), "r"(a[2]), "r"(a[3]), "r"(b0), "r"(b1));
}
__device__ __forceinline__ float wsum(float v) {
#pragma unroll
    for (int o = 16; o; o >>= 1) v += __shfl_xor_sync(0xffffffffu, v, o);
    return v;
}
__device__ __forceinline__ bool better(float v, int i, float w, int j) {
    return (v > w) || (v == w && i < j);
}

// ---------------- prep: split W into swizzled fp16 tiles ----------------
__global__ void prep_kernel(const float* __restrict__ gate_w,
                            const float* __restrict__ cap_w1) {
    int idx = blockIdx.x * blockDim.x + threadIdx.x;
    if (idx >= NOUT * DIM) return;
    int n = idx >> 12;
    int k = idx & (DIM - 1);
    float w = (n < NEXP) ? gate_w[n * DIM + k] : cap_w1[(n - NEXP) * DIM + k];
    __half wh = __float2half_rn(w);
    float res = (w - __half2float(wh)) * 2048.0f;
    __half wl = __float2half_rn(res);
    int t = k >> 6, kk = k & 63;
    int off = SW128(n * 128 + kk * 2);
    *(__half*)(g_wh + t * TILE_B + off) = wh;
    *(__half*)(g_wl + t * TILE_B + off) = wl;
}

// ---------------- main kernel: 512 threads, 16 warps ----------------
__global__ void __launch_bounds__(512, 1)
router_kernel(const float* __restrict__ x,
              const float* __restrict__ cap_b1, const float* __restrict__ ln_g,
              const float* __restrict__ ln_b,   const float* __restrict__ cap_w2,
              const float* __restrict__ cap_b2, const float* __restrict__ temp,
              const float* __restrict__ usage,  float* __restrict__ out) {
    extern __shared__ char smem[];
    const uint32_t sb = smem_u32(smem);
    const int tid  = threadIdx.x;
    const int wid  = tid >> 5;
    const int lane = tid & 31;
    const int tok0 = blockIdx.x * MT;

    // roles: p = wid>>1: 0-3 hi (N=p*32 of 128), 4-5 lo1 (xh*wl), 6-7 lo2 (xl*wh)
    const int mt      = wid & 1;
    const int p       = wid >> 1;
    const int rowbase = mt * 64;
    const int nbase   = (p < 4) ? p * 32 : (p & 1) * 32;
    const int aOff    = (p >= 6) ? OFF_XL : OFF_XH;
    const int bOff    = (p == 4 || p == 5) ? OFF_WL : OFF_WH;

    const int g  = lane >> 3;
    const int lr = lane & 7;
    const uint32_t rowA0 = (uint32_t)(rowbase + (g & 1) * 8 + lr) * 128;
    const uint32_t rowB0 = (uint32_t)(nbase   + (g & 1) * 8 + lr) * 128;
    const uint32_t kx    = (uint32_t)(((g >> 1) ^ lr) << 4);

    float acc[4][4][4];
#pragma unroll
    for (int a = 0; a < 4; a++)
#pragma unroll
        for (int b = 0; b < 4; b++)
#pragma unroll
            for (int c = 0; c < 4; c++) acc[a][b][c] = 0.0f;

    const int xr = tid >> 2, xq = tid & 3;
    const float* xptr = x + (size_t)(tok0 + xr) * DIM + xq * 16;
    const uint32_t s0 = SW128((uint32_t)(xr * 128 + xq * 32));
    const uint32_t s1 = SW128((uint32_t)(xr * 128 + xq * 32 + 16));

    auto issueW = [&](int chunk, int buf) {
        const uint32_t wdst = sb + buf * BUF_B;
        const unsigned char* whs = g_wh + chunk * TILE_B;
        const unsigned char* wls = g_wl + chunk * TILE_B;
        cp_async16(wdst + OFF_WH + tid * 16,          whs + tid * 16);
        cp_async16(wdst + OFF_WH + (tid + 512) * 16,  whs + (tid + 512) * 16);
        cp_async16(wdst + OFF_WL + tid * 16,          wls + tid * 16);
        cp_async16(wdst + OFF_WL + (tid + 512) * 16,  wls + (tid + 512) * 16);
        CP_COMMIT();
    };

    auto convert = [&](const float4* xf, int buf) {
        char* dh = smem + buf * BUF_B + OFF_XH;
        char* dl = smem + buf * BUF_B + OFF_XL;
        uint32_t hp[8], lp[8];
#pragma unroll
        for (int m = 0; m < 4; m++) {
            float4 f = xf[m];
            __half2 hA = __float22half2_rn(make_float2(f.x, f.y));
            __half2 hB = __float22half2_rn(make_float2(f.z, f.w));
            float2 gA = __half22float2(hA);
            float2 gB = __half22float2(hB);
            __half2 lA = __float22half2_rn(
                make_float2((f.x - gA.x) * 2048.0f, (f.y - gA.y) * 2048.0f));
            __half2 lB = __float22half2_rn(
                make_float2((f.z - gB.x) * 2048.0f, (f.w - gB.y) * 2048.0f));
            hp[2 * m]     = *(uint32_t*)&hA;
            hp[2 * m + 1] = *(uint32_t*)&hB;
            lp[2 * m]     = *(uint32_t*)&lA;
            lp[2 * m + 1] = *(uint32_t*)&lB;
        }
        *(uint4*)(dh + s0) = make_uint4(hp[0], hp[1], hp[2], hp[3]);
        *(uint4*)(dh + s1) = make_uint4(hp[4], hp[5], hp[6], hp[7]);
        *(uint4*)(dl + s0) = make_uint4(lp[0], lp[1], lp[2], lp[3]);
        *(uint4*)(dl + s1) = make_uint4(lp[4], lp[5], lp[6], lp[7]);
    };

    auto mmaPhase = [&](int buf) {
        const uint32_t aB = sb + buf * BUF_B + aOff + rowA0;
        const uint32_t bB = sb + buf * BUF_B + bOff + rowB0;
#pragma unroll
        for (int ks = 0; ks < 4; ks++) {
            const uint32_t ko = ((uint32_t)ks * 32) ^ kx;
            uint32_t a[4][4], b[2][4];
#pragma unroll
            for (int mi = 0; mi < 4; mi++) ldsm4(a[mi], aB + mi * 2048 + ko);
#pragma unroll
            for (int nj = 0; nj < 2; nj++) ldsm4(b[nj], bB + nj * 2048 + ko);
#pragma unroll
            for (int mi = 0; mi < 4; mi++)
#pragma unroll
                for (int nj = 0; nj < 2; nj++) {
                    mma16816(acc[mi][2 * nj],     a[mi], b[nj][0], b[nj][2]);
                    mma16816(acc[mi][2 * nj + 1], a[mi], b[nj][1], b[nj][3]);
                }
        }
    };

    // ---- prologue: W chunks 0,1 in flight; convert x chunk 0 into buf 0 ----
    float4 xf[4];
    issueW(0, 0);
    issueW(1, 1);
    {
        const float4* px = (const float4*)xptr;
#pragma unroll
        for (int m = 0; m < 4; m++) xf[m] = px[m];
    }
    convert(xf, 0);
    CP_WAIT1();                     // W chunk 0 resident
    __syncthreads();

    // ---- main loop: consume buf i%3; prefetch W i+2, x i+1 ----
#pragma unroll 1
    for (int i = 0; i < NIT; i++) {
        const int cur = i % NSTAGE;
        if (i + 2 < NIT) issueW(i + 2, (i + 2) % NSTAGE);
        if (i + 1 < NIT) {
            const float4* px = (const float4*)(xptr + (i + 1) * KC);
#pragma unroll
            for (int m = 0; m < 4; m++) xf[m] = px[m];
        }

        mmaPhase(cur);

        if (i + 1 < NIT) {
            convert(xf, (i + 1) % NSTAGE);
            if (i + 2 < NIT) { CP_WAIT1(); } else { CP_WAIT0(); }
            __syncthreads();
        }
    }
    __syncthreads();

    // ---- epilogue A: accumulators -> smem ----
    float* sc  = (float*)smem;                   // [128][129]
    float* lo1 = (float*)(smem + EPI_LO1);       // [128][65]
    float* lo2 = (float*)(smem + EPI_LO2);       // [128][65]
    {
        float* dst; int stride;
        if (p < 4)      { dst = sc;  stride = 129; }
        else if (p < 6) { dst = lo1; stride = 65;  }
        else            { dst = lo2; stride = 65;  }
        const int r4 = lane >> 2, c2 = (lane & 3) * 2;
#pragma unroll
        for (int mi = 0; mi < 4; mi++)
#pragma unroll
            for (int n8 = 0; n8 < 4; n8++) {
                int row = rowbase + mi * 16 + r4;
                int col = nbase + n8 * 8 + c2;
                dst[row * stride + col]           = acc[mi][n8][0];
                dst[row * stride + col + 1]       = acc[mi][n8][1];
                dst[(row + 8) * stride + col]     = acc[mi][n8][2];
                dst[(row + 8) * stride + col + 1] = acc[mi][n8][3];
            }
    }
    __syncthreads();

    // ---- epilogue B: per-token routing (16 warps x 8 tokens) ----
    const float u_a = usage[lane], u_b = usage[lane + 32];
    const float utot = wsum(u_a + u_b);
    const float lbs  = 0.1f / (utot + 1e-6f);
    const float lbp_a = u_a * lbs, lbp_b = u_b * lbs;
    const float tclip = fmaxf(temp[0], 0.1f);
    const float cb1a = cap_b1[lane],  cb1b = cap_b1[lane + 32];
    const float ga   = ln_g[lane],    gb   = ln_g[lane + 32];
    const float ba   = ln_b[lane],    bb   = ln_b[lane + 32];
    const float w2a  = cap_w2[lane],  w2b  = cap_w2[lane + 32];
    const float b2   = cap_b2[0];
    const float INV2048 = 4.8828125e-4f;

#pragma unroll 1
    for (int j = 0; j < 8; j++) {
        const int tl = wid * 8 + j;
        const float* srow  = sc  + tl * 129;
        const float* l1row = lo1 + tl * 65;
        const float* l2row = lo2 + tl * 65;
        const float s_a = srow[lane]      + (l1row[lane]      + l2row[lane])      * INV2048;
        const float s_b = srow[lane + 32] + (l1row[lane + 32] + l2row[lane + 32]) * INV2048;
        const float h_a = srow[64 + lane] + cb1a;
        const float h_b = srow[96 + lane] + cb1b;

        const float mu  = wsum(h_a + h_b) * (1.0f / 64.0f);
        const float msq = wsum(h_a * h_a + h_b * h_b) * (1.0f / 64.0f);
        const float rstd = rsqrtf(msq - mu * mu + 1e-5f);
        const float na = (h_a - mu) * rstd * ga + ba;
        const float nb = (h_b - mu) * rstd * gb + bb;
        const float ge_a = 0.5f * na * (1.0f + erff(na * 0.70710678118654752f));
        const float ge_b = 0.5f * nb * (1.0f + erff(nb * 0.70710678118654752f));
        const float z = wsum(ge_a * w2a + ge_b * w2b) + b2;
        const float cap = 1.0f / (1.0f + expf(-z));
        const float scale = cap * tclip;

        const float gta = (s_a - lbp_a) * scale;
        const float gtb = (s_b - lbp_b) * scale;

        float v1, v2; int i1, i2;
        if (better(gta, lane, gtb, lane + 32)) { v1 = gta; i1 = lane;      v2 = gtb; i2 = lane + 32; }
        else                                   { v1 = gtb; i1 = lane + 32; v2 = gta; i2 = lane; }
#pragma unroll
        for (int o = 16; o; o >>= 1) {
            float ov1 = __shfl_xor_sync(0xffffffffu, v1, o);
            int   oi1 = __shfl_xor_sync(0xffffffffu, i1, o);
            float ov2 = __shfl_xor_sync(0xffffffffu, v2, o);
            int   oi2 = __shfl_xor_sync(0xffffffffu, i2, o);
            if (better(ov1, oi1, v1, i1)) {
                float c2v; int c2i;
                if (better(v1, i1, ov2, oi2)) { c2v = v1; c2i = i1; }
                else                          { c2v = ov2; c2i = oi2; }
                v1 = ov1; i1 = oi1; v2 = c2v; i2 = c2i;
            } else if (better(ov1, oi1, v2, i2)) {
                v2 = ov1; i2 = oi1;
            }
        }
        const float inv = 1.0f / (v1 + v2 + 1e-6f);
        const size_t ob = (size_t)(tok0 + tl) * 64;
        out[ob + lane]      = (lane == i1)      ? v1 * inv : ((lane == i2)      ? v2 * inv : 0.0f);
        out[ob + lane + 32] = (lane + 32 == i1) ? v1 * inv : ((lane + 32 == i2) ? v2 * inv : 0.0f);
    }
}

// ---------------- launch ----------------
extern "C" void kernel_launch(void* const* d_in, const int* in_sizes, int n_in,
                              void* d_out, int out_size) {
    const float* x      = (const float*)d_in[0];
    const float* gate_w = (const float*)d_in[1];
    const float* cap_w1 = (const float*)d_in[2];
    const float* cap_b1 = (const float*)d_in[3];
    const float* ln_g   = (const float*)d_in[4];
    const float* ln_b   = (const float*)d_in[5];
    const float* cap_w2 = (const float*)d_in[6];
    const float* cap_b2 = (const float*)d_in[7];
    const float* temp   = (const float*)d_in[8];
    const float* usage  = (const float*)d_in[9];
    float* out = (float*)d_out;

    cudaFuncSetAttribute(router_kernel,
                         cudaFuncAttributeMaxDynamicSharedMemorySize, SMEM_SZ);

    prep_kernel<<<(NOUT * DIM) / 256, 256>>>(gate_w, cap_w1);
    router_kernel<<<NTOK / MT, 512, SMEM_SZ>>>(x, cap_b1, ln_g, ln_b, cap_w2,
                                               cap_b2, temp, usage, out);
}